// round 7
// baseline (speedup 1.0000x reference)
#include <cuda_runtime.h>
#include <cuda_bf16.h>

// DensityEstimator: per-channel 1->3->3->3->1 MLP, p = cdf(x+.5) - cdf(x-.5)
// R7: 3 elements/thread = 6 independent tanh chains, fused per-layer so ptxas
// interleaves them (latency cover for MUFU.TANH lat=16/rt=8). 64-reg cap keeps
// 4 blocks/SM resident; a few cold weights spill to local (lane-coalesced LDL,
// ~10/elem << MUFU floor). Grid 591 (== 0 mod 3): 591*256 % 192 == 0 so the
// channel is fixed per thread; ~3.99 blocks/SM -> single wave.

#define NCH  192
#define NBLK 591
#define NTHR 256
#define E    3            // elements per thread per iteration

__device__ __forceinline__ float tanha(float x) {
    float r; asm("tanh.approx.f32 %0, %1;" : "=f"(r) : "f"(x)); return r;
}
__device__ __forceinline__ float softplus_acc(float h) {
    return (h > 15.0f) ? h : log1pf(expf(h));
}

__global__ void __launch_bounds__(NTHR, 4) de_kernel(
    const float* __restrict__ x,
    const float* __restrict__ a0, const float* __restrict__ a1, const float* __restrict__ a2,
    const float* __restrict__ b0, const float* __restrict__ b1, const float* __restrict__ b2,
    const float* __restrict__ b3,
    const float* __restrict__ H0, const float* __restrict__ H1, const float* __restrict__ H2,
    const float* __restrict__ H3,
    float* __restrict__ out, int n)
{
    const int T  = gridDim.x * blockDim.x;          // 151296, multiple of 192
    const int i0 = blockIdx.x * blockDim.x + threadIdx.x;
    const int c  = i0 % NCH;                        // fixed channel (T % 192 == 0)

    // One-time per-thread weight transform (40 values; hot ones stay in regs,
    // cold ones may spill under the 64-reg cap -- that's intended).
    float sh0[3], sh1[9], sh2[9], sh3[3];
    float ta0[3], ta1[3], ta2[3];
    float bp0[3], bb1[3], bb2[3], bb3;
#pragma unroll
    for (int j = 0; j < 3; j++) {
        sh0[j] = softplus_acc(__ldg(&H0[c*3 + j]));          // H0: (C,1,3)
        sh3[j] = 0.5f * softplus_acc(__ldg(&H3[c*3 + j]));   // H3: (C,3,1), 1/2 folded
        ta0[j] = tanhf(__ldg(&a0[c*3 + j]));
        ta1[j] = tanhf(__ldg(&a1[c*3 + j]));
        ta2[j] = tanhf(__ldg(&a2[c*3 + j]));
        bp0[j] = fmaf(0.5f, sh0[j], __ldg(&b0[c*3 + j]));    // x+0.5 folded
        bb1[j] = __ldg(&b1[c*3 + j]);
        bb2[j] = __ldg(&b2[c*3 + j]);
    }
#pragma unroll
    for (int j = 0; j < 9; j++) {
        sh1[j] = softplus_acc(__ldg(&H1[c*9 + j]));          // H1: (C,3,3) [i*3+p]
        sh2[j] = softplus_acc(__ldg(&H2[c*9 + j]));
    }
    bb3 = 0.5f * __ldg(&b3[c]);                              // 1/2 folded

    // Three elements per iteration; i, i+T, i+2T share the channel.
    for (int i = i0; i < n; i += E * T) {
        float xv[E];
        bool  ok[E];
#pragma unroll
        for (int e = 0; e < E; e++) {
            int ie = i + e * T;
            ok[e] = ie < n;
            xv[e] = x[ok[e] ? ie : i];
        }

        // ---- Layer 0: 1 -> 3 (m-branch arg = p-branch arg - sh0, exact) ----
        float yp[E][3], ym[E][3];
#pragma unroll
        for (int j = 0; j < 3; j++) {
#pragma unroll
            for (int e = 0; e < E; e++) {
                float tp = fmaf(xv[e], sh0[j], bp0[j]);
                float tm = tp - sh0[j];
                yp[e][j] = fmaf(ta0[j], tanha(tp), tp);
                ym[e][j] = fmaf(ta0[j], tanha(tm), tm);
            }
        }

        // ---- Layer 1: 3 -> 3 ----
        float zp[E][3], zm[E][3];
#pragma unroll
        for (int p = 0; p < 3; p++) {
#pragma unroll
            for (int e = 0; e < E; e++) {
                float sp = bb1[p], sm = bb1[p];
#pragma unroll
                for (int j = 0; j < 3; j++) {
                    sp = fmaf(yp[e][j], sh1[j*3 + p], sp);
                    sm = fmaf(ym[e][j], sh1[j*3 + p], sm);
                }
                zp[e][p] = fmaf(ta1[p], tanha(sp), sp);
                zm[e][p] = fmaf(ta1[p], tanha(sm), sm);
            }
        }

        // ---- Layer 2: 3 -> 3 (overwrite yp/ym) ----
#pragma unroll
        for (int p = 0; p < 3; p++) {
#pragma unroll
            for (int e = 0; e < E; e++) {
                float sp = bb2[p], sm = bb2[p];
#pragma unroll
                for (int j = 0; j < 3; j++) {
                    sp = fmaf(zp[e][j], sh2[j*3 + p], sp);
                    sm = fmaf(zm[e][j], sh2[j*3 + p], sm);
                }
                yp[e][p] = fmaf(ta2[p], tanha(sp), sp);
                ym[e][p] = fmaf(ta2[p], tanha(sm), sm);
            }
        }

        // ---- Layer 3 + tanh-form sigmoid difference ----
#pragma unroll
        for (int e = 0; e < E; e++) {
            float fp = bb3, fm = bb3;
#pragma unroll
            for (int j = 0; j < 3; j++) {
                fp = fmaf(yp[e][j], sh3[j], fp);
                fm = fmaf(ym[e][j], sh3[j], fm);
            }
            float r = 0.5f * (tanha(fp) - tanha(fm));
            if (ok[e]) out[i + e * T] = r;
        }
    }
}

extern "C" void kernel_launch(void* const* d_in, const int* in_sizes, int n_in,
                              void* d_out, int out_size)
{
    const float* x  = (const float*)d_in[0];
    const float* a0 = (const float*)d_in[1];
    const float* a1 = (const float*)d_in[2];
    const float* a2 = (const float*)d_in[3];
    const float* b0 = (const float*)d_in[4];
    const float* b1 = (const float*)d_in[5];
    const float* b2 = (const float*)d_in[6];
    const float* b3 = (const float*)d_in[7];
    const float* H0 = (const float*)d_in[8];
    const float* H1 = (const float*)d_in[9];
    const float* H2 = (const float*)d_in[10];
    const float* H3 = (const float*)d_in[11];
    float* out = (float*)d_out;
    int n = in_sizes[0];   // 65536 * 192

    de_kernel<<<NBLK, NTHR>>>(x, a0, a1, a2, b0, b1, b2, b3,
                              H0, H1, H2, H3, out, n);
}